// round 16
// baseline (speedup 1.0000x reference)
#include <cuda_runtime.h>
#include <cuda_bf16.h>

typedef __nv_bfloat16 bf16;
typedef unsigned int u32;

#define E_ 512
#define H_ 1024
#define B_ 64
#define T_ 64
#define TD_ 63
#define V_ 32000
#define G_ 4096
#define NCH 250
#define AS_ 40
#define AST 72
#define EST 1048
#define SGS 68
#define KST 136

// ---------------- device scratch ----------------
__device__ bf16 g_WihF[G_*E_];
__device__ bf16 g_WhhF[G_*H_];
__device__ bf16 g_WihB[G_*E_];
__device__ bf16 g_WhhB[G_*H_];
__device__ bf16 g_Wihd[G_*(E_+H_)];
__device__ bf16 g_Wdec[G_*2048];
__device__ bf16 g_Whp[H_*2048];
__device__ bf16 g_Wcp[H_*2048];
__device__ bf16 g_Watt[H_*2048];
__device__ bf16 g_Wcomb[H_*3072];
__device__ bf16 g_Wvoc[V_*H_];
__device__ float g_bEncF[G_], g_bEncB[G_], g_bDec[G_];
__device__ bf16 g_Xg[T_*B_*E_];
__device__ bf16 g_Yg[4096*E_];
__device__ float g_GxF[T_*B_*G_];
__device__ float g_GxB[T_*B_*G_];
__device__ float g_Gy[4096*G_];
__device__ float g_hf[B_*H_], g_cf[B_*H_], g_hb[B_*H_], g_cb[B_*H_];
__device__ bf16 g_hfh[B_*H_], g_hbh[B_*H_];
__device__ bf16 g_ench[B_*T_*2048];
__device__ bf16 g_encproj[B_*T_*H_];
__device__ bf16 g_hcat[B_*2048], g_ccat[B_*2048];
__device__ float g_cdec[B_*H_];
__device__ bf16 g_acat[B_*2048];
__device__ float g_gates[B_*G_];
__device__ bf16 g_combin[B_*3072];
__device__ bf16 g_outs[4096*H_];
__device__ float g_pmax[TD_*B_*NCH], g_psum[TD_*B_*NCH], g_pgold[TD_*B_];
__device__ unsigned int g_barCnt;
__device__ unsigned int g_barGen;

// ---------------- helpers ----------------
__device__ __forceinline__ float sigf(float x){ return 1.f/(1.f+expf(-x)); }

__device__ __forceinline__ void mma16816(float* c, const u32* a, const u32* b){
    asm volatile("mma.sync.aligned.m16n8k16.row.col.f32.bf16.bf16.f32 "
        "{%0,%1,%2,%3},{%4,%5,%6,%7},{%8,%9},{%0,%1,%2,%3};\n"
        : "+f"(c[0]),"+f"(c[1]),"+f"(c[2]),"+f"(c[3])
        : "r"(a[0]),"r"(a[1]),"r"(a[2]),"r"(a[3]),"r"(b[0]),"r"(b[1]));
}
__device__ __forceinline__ void ldm_x4(u32* r, u32 addr){
    asm volatile("ldmatrix.sync.aligned.m8n8.x4.shared.b16 {%0,%1,%2,%3}, [%4];\n"
        : "=r"(r[0]),"=r"(r[1]),"=r"(r[2]),"=r"(r[3]) : "r"(addr));
}
__device__ __forceinline__ void ldm_x2(u32* r, u32 addr){
    asm volatile("ldmatrix.sync.aligned.m8n8.x2.shared.b16 {%0,%1}, [%2];\n"
        : "=r"(r[0]),"=r"(r[1]) : "r"(addr));
}
__device__ __forceinline__ void cpasync16(void* sdst, const void* gsrc){
    u32 s = (u32)__cvta_generic_to_shared(sdst);
    asm volatile("cp.async.ca.shared.global [%0], [%1], 16;\n" :: "r"(s), "l"(gsrc));
}
__device__ __forceinline__ void cpcommit(){ asm volatile("cp.async.commit_group;\n"); }
template<int N> __device__ __forceinline__ void cpwait(){ asm volatile("cp.async.wait_group %0;\n"::"n"(N)); }

__global__ void barResetK(){ g_barCnt=0; g_barGen=0; }

__device__ __forceinline__ void gridBar(unsigned int nCTA, unsigned int &myGen){
    __syncthreads();
    myGen++;
    if(threadIdx.x==0){
        __threadfence();
        unsigned int a = atomicAdd(&g_barCnt, 1);
        if(a == nCTA-1){
            g_barCnt = 0;
            __threadfence();
            atomicExch(&g_barGen, myGen);
        } else {
            while(true){
                unsigned int v = *((volatile unsigned int*)&g_barGen);
                if(v >= myGen) break;
                __nanosleep(32);
            }
            __threadfence();
        }
    }
    __syncthreads();
}

#define LDM_SETUP() \
    u32 arow = (lane&7) + ((lane>>3)&1)*8; \
    u32 acol = (lane>>4)*8; \
    u32 brow = (lane&7) + ((lane>>4)&1)*8; \
    u32 bcol = ((lane>>3)&1)*8;

// ---------------- prep megakernel ----------------
__device__ __forceinline__ u32 pack2(float x, float y){
    __nv_bfloat162 h = __floats2bfloat162_rn(x, y);
    return *(u32*)&h;
}
__global__ void prepK(
    const float* __restrict__ WihF, const float* __restrict__ WhhF,
    const float* __restrict__ WihB, const float* __restrict__ WhhB,
    const float* __restrict__ Wihd, const float* __restrict__ Whhd,
    const float* __restrict__ Whp,  const float* __restrict__ Wcp,
    const float* __restrict__ Watt, const float* __restrict__ Wcmb,
    const float* __restrict__ Wvoc,
    const float* __restrict__ bihF, const float* __restrict__ bhhF,
    const float* __restrict__ bihB, const float* __restrict__ bhhB,
    const float* __restrict__ bihd, const float* __restrict__ bhhd,
    const int* __restrict__ srcTok, const int* __restrict__ tgtTok,
    const float* __restrict__ srcEmb, const float* __restrict__ dstEmb)
{
    int stride = gridDim.x*blockDim.x;
    int t0 = blockIdx.x*blockDim.x + threadIdx.x;
    auto cvt4 = [&](const float* s, bf16* d, int n){
        const float4* s4 = (const float4*)s;
        uint2* d4 = (uint2*)d;
        int n4 = n>>2;
        for(int i=t0;i<n4;i+=stride){
            float4 v = s4[i];
            uint2 o; o.x = pack2(v.x,v.y); o.y = pack2(v.z,v.w);
            d4[i] = o;
        }
    };
    cvt4(WihF, g_WihF, G_*E_);
    cvt4(WihB, g_WihB, G_*E_);
    cvt4(Wihd, g_Wihd, G_*1536);
    cvt4(Whp,  g_Whp,  H_*2048);
    cvt4(Wcp,  g_Wcp,  H_*2048);
    cvt4(Watt, g_Watt, H_*2048);
    cvt4(Wcmb, g_Wcomb,H_*3072);
    cvt4(Wvoc, g_Wvoc, V_*H_);
    for(int i=t0;i<(G_*H_)>>2;i+=stride){
        int p=i>>8, k4=i&255;
        int nb=p>>6, c=p&63, q=c>>4, jj=c&15;
        float4 v = *(const float4*)(WhhF + (size_t)(q*1024+nb*16+jj)*1024 + k4*4);
        uint2 o; o.x=pack2(v.x,v.y); o.y=pack2(v.z,v.w);
        *(uint2*)(g_WhhF + (size_t)p*1024 + k4*4) = o;
    }
    for(int i=t0;i<(G_*H_)>>2;i+=stride){
        int p=i>>8, k4=i&255;
        int nb=p>>6, c=p&63, q=c>>4, jj=c&15;
        float4 v = *(const float4*)(WhhB + (size_t)(q*1024+nb*16+jj)*1024 + k4*4);
        uint2 o; o.x=pack2(v.x,v.y); o.y=pack2(v.z,v.w);
        *(uint2*)(g_WhhB + (size_t)p*1024 + k4*4) = o;
    }
    for(int i=t0;i<(G_*2048)>>2;i+=stride){
        int n=i>>9, k=(i&511)*4;
        const float* s = (k<1024)? (Whhd + (size_t)n*1024 + k)
                                 : (Wihd + (size_t)n*1536 + 512 + (k-1024));
        float4 v = *(const float4*)s;
        uint2 o; o.x=pack2(v.x,v.y); o.y=pack2(v.z,v.w);
        *(uint2*)(g_Wdec + (size_t)n*2048 + k) = o;
    }
    for(int i=t0;i<(T_*B_*E_)>>2;i+=stride){
        int r=i>>7, c4=i&127;
        float4 v = *(const float4*)(srcEmb + (size_t)srcTok[r]*E_ + c4*4);
        uint2 o; o.x=pack2(v.x,v.y); o.y=pack2(v.z,v.w);
        *(uint2*)(g_Xg + (size_t)r*E_ + c4*4) = o;
    }
    for(int i=t0;i<(TD_*B_*E_)>>2;i+=stride){
        int r=i>>7, c4=i&127;
        float4 v = *(const float4*)(dstEmb + (size_t)tgtTok[r]*E_ + c4*4);
        uint2 o; o.x=pack2(v.x,v.y); o.y=pack2(v.z,v.w);
        *(uint2*)(g_Yg + (size_t)r*E_ + c4*4) = o;
    }
    for(int i=t0;i<G_;i+=stride){
        g_bEncF[i]=bihF[i]+bhhF[i];
        g_bEncB[i]=bihB[i]+bhhB[i];
        g_bDec[i]=bihd[i]+bhhd[i];
    }
    for(int i=t0;i<B_*H_;i+=stride){
        g_hf[i]=0.f; g_cf[i]=0.f; g_hb[i]=0.f; g_cb[i]=0.f;
        bf16 z=__float2bfloat16(0.f);
        g_hfh[i]=z; g_hbh[i]=z;
        g_acat[(i>>10)*2048 + 1024 + (i&1023)] = z;
    }
    for(int i=t0;i<64*E_;i+=stride) g_Yg[4032*E_ + i]=__float2bfloat16(0.f);
    for(int i=t0;i<64*H_;i+=stride) g_outs[(size_t)4032*H_ + i]=__float2bfloat16(0.f);
}

// ---------------- gemm128: 3-stage, single sync ----------------
__global__ void __launch_bounds__(256) gemm128(
    const bf16* __restrict__ A, int lda,
    const bf16* __restrict__ Bw, int ldb,
    float* C, int ldc, int outBf16,
    int dmode, const float* __restrict__ D, int K)
{
    extern __shared__ __align__(16) bf16 gsm[];
    const int STG = 128*AS_;
    int tid=threadIdx.x, warp=tid>>5, lane=tid&31, g=lane>>2, tg=lane&3;
    int wr=warp>>1, wc=warp&1;
    LDM_SETUP();
    u32 gsmU = (u32)__cvta_generic_to_shared(gsm);
    int bm=blockIdx.y*128, bn=blockIdx.x*128;
    float acc[2][8][4];
    #pragma unroll
    for(int i=0;i<2;i++) for(int j=0;j<8;j++) for(int k=0;k<4;k++) acc[i][j][k]=0.f;
    int nIt = K>>5;
    auto ld = [&](int it, int s){
        bf16* As = gsm + s*2*STG; bf16* Bs = As + STG;
        #pragma unroll
        for(int i=tid;i<512;i+=256){ int r=i>>2, c=(i&3)*8;
            cpasync16(&As[r*AS_+c], A + (size_t)(bm+r)*lda + it*32 + c); }
        #pragma unroll
        for(int i=tid;i<512;i+=256){ int r=i>>2, c=(i&3)*8;
            cpasync16(&Bs[r*AS_+c], Bw + (size_t)(bn+r)*ldb + it*32 + c); }
        cpcommit();
    };
    ld(0,0); ld(1,1);
    for(int it=0; it<nIt; it++){
        if(it+1<nIt) cpwait<1>(); else cpwait<0>();
        __syncthreads();
        if(it+2<nIt) ld(it+2, (it+2)%3);
        u32 AsU = gsmU + (it%3)*2*STG*2; u32 BsU = AsU + STG*2;
        #pragma unroll
        for(int kk=0;kk<32;kk+=16){
            u32 a[2][4], b[8][2];
            #pragma unroll
            for(int mi=0;mi<2;mi++)
                ldm_x4(a[mi], AsU + ((wr*32+mi*16+arow)*AS_ + kk + acol)*2);
            #pragma unroll
            for(int nj=0;nj<4;nj++)
                ldm_x4(&b[nj*2][0], BsU + ((wc*64+nj*16+brow)*AS_ + kk + bcol)*2);
            #pragma unroll
            for(int mi=0;mi<2;mi++)
                #pragma unroll
                for(int ni=0;ni<8;ni++)
                    mma16816(acc[mi][ni], a[mi], b[ni]);
        }
    }
    #pragma unroll
    for(int mi=0;mi<2;mi++){
        #pragma unroll
        for(int ni=0;ni<8;ni++){
            int r0 = bm + wr*32 + mi*16 + g;
            int c0 = bn + wc*64 + ni*8 + tg*2;
            float v0=acc[mi][ni][0], v1=acc[mi][ni][1], v2=acc[mi][ni][2], v3=acc[mi][ni][3];
            if(dmode==1){ v0+=D[c0]; v1+=D[c0+1]; v2+=D[c0]; v3+=D[c0+1]; }
            if(outBf16){
                bf16* Cb=(bf16*)C;
                Cb[(size_t)r0*ldc+c0]=__float2bfloat16(v0);
                Cb[(size_t)r0*ldc+c0+1]=__float2bfloat16(v1);
                Cb[(size_t)(r0+8)*ldc+c0]=__float2bfloat16(v2);
                Cb[(size_t)(r0+8)*ldc+c0+1]=__float2bfloat16(v3);
            } else {
                C[(size_t)r0*ldc+c0]=v0; C[(size_t)r0*ldc+c0+1]=v1;
                C[(size_t)(r0+8)*ldc+c0]=v2; C[(size_t)(r0+8)*ldc+c0+1]=v3;
            }
        }
    }
}

// ---------------- gemm64 (R9 pattern) ----------------
__global__ void __launch_bounds__(128) gemm64(
    const bf16* __restrict__ A, int lda,
    const bf16* __restrict__ Bw, int ldb,
    float* C, int ldc, int outBf16, int K)
{
    __shared__ __align__(16) bf16 As[2][64*AS_];
    __shared__ __align__(16) bf16 Bs[2][64*AS_];
    int tid=threadIdx.x, warp=tid>>5, lane=tid&31, g=lane>>2, tg=lane&3;
    int wr=warp>>1, wc=warp&1;
    LDM_SETUP();
    u32 AsU0 = (u32)__cvta_generic_to_shared(&As[0][0]);
    u32 BsU0 = (u32)__cvta_generic_to_shared(&Bs[0][0]);
    int bm=blockIdx.y*64, bn=blockIdx.x*64;
    float acc[2][4][4];
    #pragma unroll
    for(int i=0;i<2;i++) for(int j=0;j<4;j++) for(int k=0;k<4;k++) acc[i][j][k]=0.f;
    int nIt = K>>5;
    auto loadTile = [&](int it, int buf){
        #pragma unroll
        for(int i=tid;i<256;i+=128){ int r=i>>2, c=(i&3)*8;
            cpasync16(&As[buf][r*AS_+c], A + (size_t)(bm+r)*lda + it*32 + c); }
        #pragma unroll
        for(int i=tid;i<256;i+=128){ int r=i>>2, c=(i&3)*8;
            cpasync16(&Bs[buf][r*AS_+c], Bw + (size_t)(bn+r)*ldb + it*32 + c); }
        cpcommit();
    };
    loadTile(0,0);
    for(int it=0; it<nIt; it++){
        int cur=it&1;
        if(it+1<nIt){ loadTile(it+1, cur^1); cpwait<1>(); } else cpwait<0>();
        __syncthreads();
        u32 AsU = AsU0 + cur*64*AS_*2;
        u32 BsU = BsU0 + cur*64*AS_*2;
        #pragma unroll
        for(int kk=0;kk<32;kk+=16){
            u32 a[2][4], b[4][2];
            #pragma unroll
            for(int mi=0;mi<2;mi++)
                ldm_x4(a[mi], AsU + ((wr*32+mi*16+arow)*AS_ + kk + acol)*2);
            #pragma unroll
            for(int nj=0;nj<2;nj++)
                ldm_x4(&b[nj*2][0], BsU + ((wc*32+nj*16+brow)*AS_ + kk + bcol)*2);
            #pragma unroll
            for(int mi=0;mi<2;mi++)
                #pragma unroll
                for(int ni=0;ni<4;ni++)
                    mma16816(acc[mi][ni], a[mi], b[ni]);
        }
        __syncthreads();
    }
    #pragma unroll
    for(int mi=0;mi<2;mi++){
        #pragma unroll
        for(int ni=0;ni<4;ni++){
            int r0 = bm + wr*32 + mi*16 + g;
            int c0 = bn + wc*32 + ni*8 + tg*2;
            if(outBf16){
                bf16* Cb=(bf16*)C;
                Cb[(size_t)r0*ldc+c0]=__float2bfloat16(acc[mi][ni][0]);
                Cb[(size_t)r0*ldc+c0+1]=__float2bfloat16(acc[mi][ni][1]);
                Cb[(size_t)(r0+8)*ldc+c0]=__float2bfloat16(acc[mi][ni][2]);
                Cb[(size_t)(r0+8)*ldc+c0+1]=__float2bfloat16(acc[mi][ni][3]);
            } else {
                C[(size_t)r0*ldc+c0]=acc[mi][ni][0]; C[(size_t)r0*ldc+c0+1]=acc[mi][ni][1];
                C[(size_t)(r0+8)*ldc+c0]=acc[mi][ni][2]; C[(size_t)(r0+8)*ldc+c0+1]=acc[mi][ni][3];
            }
        }
    }
}

// ---------------- persistent encoder (R9 pattern) ----------------
__global__ void __launch_bounds__(256) encPersist(const int* __restrict__ lens){
    extern __shared__ __align__(16) bf16 esm[];
    bf16* Ws  = esm;
    bf16* As0 = esm + 64*EST;
    bf16* As1 = As0 + 64*AST;
    float* sgate = (float*)As0;
    __shared__ int slen[64];
    int tid=threadIdx.x, warp=tid>>5, lane=tid&31, g=lane>>2, tg=lane&3;
    int wr=warp>>1, wc=warp&1;
    LDM_SETUP();
    u32 WsU  = (u32)__cvta_generic_to_shared(Ws);
    u32 As0U = (u32)__cvta_generic_to_shared(As0);
    u32 As1U = (u32)__cvta_generic_to_shared(As1);
    int dir = blockIdx.x>>6, nb = blockIdx.x&63;
    const bf16* W = (dir? g_WhhB : g_WhhF) + (size_t)nb*64*1024;
    const bf16* hsrc = dir? g_hbh : g_hfh;
    const float* Gx = dir? g_GxB : g_GxF;
    float* hs = dir ? g_hb : g_hf;
    float* cs = dir ? g_cb : g_cf;
    bf16* hh = dir ? g_hbh : g_hfh;
    unsigned int myGen = 0;

    if(tid<64) slen[tid]=lens[tid];
    for(int i=tid;i<8192;i+=256){
        int r=i>>7, c=(i&127)*8;
        *(uint4*)&Ws[r*EST+c] = *(const uint4*)(W + r*1024 + c);
    }
    __syncthreads();

    for(int t=0;t<64;t++){
        int time = dir? (63-t) : t;
        float acc[4][4];
        #pragma unroll
        for(int i=0;i<4;i++) for(int j=0;j<4;j++) acc[i][j]=0.f;

        #pragma unroll
        for(int i=tid;i<512;i+=256){ int r=i>>3, c=(i&7)*8;
            cpasync16(&As0[r*AST+c], hsrc + r*1024 + c); }
        cpcommit();

        #pragma unroll
        for(int it=0; it<16; it++){
            u32 curU = (it&1)? As1U : As0U;
            bf16* nxt = (it&1)? As0 : As1;
            if(it<15){
                #pragma unroll
                for(int i=tid;i<512;i+=256){ int r=i>>3, c=(i&7)*8;
                    cpasync16(&nxt[r*AST+c], hsrc + r*1024 + (it+1)*64 + c); }
                cpcommit();
                cpwait<1>();
            } else cpwait<0>();
            __syncthreads();
            #pragma unroll
            for(int kk=0;kk<64;kk+=16){
                u32 a[4], b[4][2];
                ldm_x4(a, curU + ((wr*16+arow)*AST + kk + acol)*2);
                #pragma unroll
                for(int nj=0;nj<2;nj++)
                    ldm_x4(&b[nj*2][0], WsU + ((wc*32+nj*16+brow)*EST + it*64 + kk + bcol)*2);
                #pragma unroll
                for(int ni=0;ni<4;ni++) mma16816(acc[ni], a, b[ni]);
            }
            __syncthreads();
        }
        #pragma unroll
        for(int ni=0;ni<4;ni++){
            int c  = wc*32 + ni*8 + tg*2;
            int oc = (c>>4)*1024 + nb*16 + (c&15);
            int r0 = wr*16 + g;
            const float* gx0 = Gx + ((size_t)time*B_ + r0)*G_ + oc;
            const float* gx1 = gx0 + 8*G_;
            sgate[r0*SGS + c]       = acc[ni][0] + gx0[0];
            sgate[r0*SGS + c + 1]   = acc[ni][1] + gx0[1];
            sgate[(r0+8)*SGS + c]   = acc[ni][2] + gx1[0];
            sgate[(r0+8)*SGS + c+1] = acc[ni][3] + gx1[1];
        }
        __syncthreads();
        #pragma unroll
        for(int idx=tid; idx<1024; idx+=256){
            int b=idx>>4, jj=idx&15;
            float gi=sgate[b*SGS+jj], gf=sgate[b*SGS+16+jj];
            float gc=sgate[b*SGS+32+jj], go=sgate[b*SGS+48+jj];
            int r = b*1024 + nb*16 + jj;
            float c=cs[r], h=hs[r];
            float c2 = sigf(gf)*c + sigf(gi)*tanhf(gc);
            float h2 = sigf(go)*tanhf(c2);
            bool m = time < slen[b];
            float hn = m?h2:h, cn = m?c2:c;
            hs[r]=hn; cs[r]=cn; hh[r]=__float2bfloat16(hn);
            g_ench[(size_t)(b*64+time)*2048 + dir*1024 + nb*16+jj] = __float2bfloat16(m?h2:0.f);
        }
        gridBar(128, myGen);
    }
}

// ---------------- persistent decoder (R9 pattern) ----------------
__global__ void __launch_bounds__(256) decPersist(const int* __restrict__ lens){
    extern __shared__ __align__(16) bf16 dsm[];
    __shared__ float h2s[1024];
    __shared__ float salpha[64];
    __shared__ float cstate[1024];
    int tid=threadIdx.x, warp=tid>>5, lane=tid&31, g=lane>>2, tg=lane&3;
    int wg = warp>>2, w4 = warp&3, wr2 = w4>>1, wc2 = w4&1;
    LDM_SETUP();
    u32 dsmU = (u32)__cvta_generic_to_shared(dsm);
    int nb = blockIdx.x;
    int b  = blockIdx.x;
    unsigned int myGen = 0;

    for(int j=tid;j<1024;j+=256) cstate[j]=g_cdec[b*1024+j];
    __syncthreads();

    for(int t=0;t<TD_;t++){
        // ---- phase 1
        {
            float acc[2][4][4];
            #pragma unroll
            for(int i=0;i<2;i++) for(int j=0;j<4;j++) for(int k=0;k<4;k++) acc[i][j][k]=0.f;
            auto loadT = [&](int it, int buf){
                bf16* Av = dsm + buf*17408;
                bf16* Bv = Av + 8704;
                #pragma unroll
                for(int i=tid;i<1024;i+=256){ int r=i>>4, c=(i&15)*8;
                    cpasync16(&Av[r*KST+c], g_acat + (size_t)r*2048 + it*128 + c); }
                #pragma unroll
                for(int i=tid;i<1024;i+=256){ int r=i>>4, c=(i&15)*8;
                    cpasync16(&Bv[r*KST+c], g_Wdec + (size_t)(nb*64+r)*2048 + it*128 + c); }
                cpcommit();
            };
            loadT(0,0);
            for(int it=0; it<16; it++){
                int cur=it&1;
                if(it<15){ loadT(it+1, cur^1); cpwait<1>(); } else cpwait<0>();
                __syncthreads();
                u32 AsU = dsmU + cur*34816;
                u32 BsU = AsU + 17408;
                int kb = wg*64;
                #pragma unroll
                for(int kk=0;kk<64;kk+=16){
                    u32 a[2][4], bb[4][2];
                    #pragma unroll
                    for(int mi=0;mi<2;mi++)
                        ldm_x4(a[mi], AsU + ((wr2*32+mi*16+arow)*KST + kb+kk + acol)*2);
                    #pragma unroll
                    for(int nj=0;nj<2;nj++)
                        ldm_x4(&bb[nj*2][0], BsU + ((wc2*32+nj*16+brow)*KST + kb+kk + bcol)*2);
                    #pragma unroll
                    for(int mi=0;mi<2;mi++)
                        #pragma unroll
                        for(int ni=0;ni<4;ni++)
                            mma16816(acc[mi][ni], a[mi], bb[ni]);
                }
                __syncthreads();
            }
            float* ps = (float*)dsm;
            if(wg==1){
                #pragma unroll
                for(int mi=0;mi<2;mi++)
                #pragma unroll
                for(int ni=0;ni<4;ni++){
                    int r0=wr2*32+mi*16+g, c0=wc2*32+ni*8+tg*2;
                    ps[r0*68+c0]  =acc[mi][ni][0]; ps[r0*68+c0+1]  =acc[mi][ni][1];
                    ps[(r0+8)*68+c0]=acc[mi][ni][2]; ps[(r0+8)*68+c0+1]=acc[mi][ni][3];
                }
            }
            __syncthreads();
            if(wg==0){
                #pragma unroll
                for(int mi=0;mi<2;mi++)
                #pragma unroll
                for(int ni=0;ni<4;ni++){
                    int r0=wr2*32+mi*16+g, c0=wc2*32+ni*8+tg*2;
                    int c = nb*64 + c0;
                    const float* gy0 = g_Gy + ((size_t)t*B_ + r0)*G_ + c;
                    const float* gy1 = gy0 + 8*G_;
                    float* gg0 = g_gates + (size_t)r0*G_ + c;
                    float* gg1 = gg0 + 8*G_;
                    gg0[0]=acc[mi][ni][0]+ps[r0*68+c0]+gy0[0];
                    gg0[1]=acc[mi][ni][1]+ps[r0*68+c0+1]+gy0[1];
                    gg1[0]=acc[mi][ni][2]+ps[(r0+8)*68+c0]+gy1[0];
                    gg1[1]=acc[mi][ni][3]+ps[(r0+8)*68+c0+1]+gy1[1];
                }
            }
        }
        gridBar(64, myGen);
        // ---- phase 2: cell + attention
        {
            const float* gg = g_gates + (size_t)b*G_;
            for(int j=tid;j<1024;j+=256){
                float gi=gg[j], gf=gg[1024+j], gc=gg[2048+j], go=gg[3072+j];
                float c = cstate[j];
                float c2 = sigf(gf)*c + sigf(gi)*tanhf(gc);
                float h2 = sigf(go)*tanhf(c2);
                cstate[j]=c2; h2s[j]=h2;
                bf16 hb=__float2bfloat16(h2);
                g_acat[(size_t)b*2048 + j] = hb;
                g_combin[(size_t)b*3072 + 2048 + j] = hb;
            }
            __syncthreads();
            int L = lens[b];
            for(int tt=warp; tt<64; tt+=8){
                const bf16* ep = g_encproj + (size_t)(b*64+tt)*1024;
                float s=0.f;
                for(int k=lane;k<1024;k+=32) s += __bfloat162float(ep[k])*h2s[k];
                for(int o=16;o;o>>=1) s += __shfl_xor_sync(0xffffffffu,s,o);
                if(lane==0) salpha[tt] = (tt<L)? s : -1e30f;
            }
            __syncthreads();
            if(warp==0){
                float e0=salpha[lane], e1=salpha[lane+32];
                float m=fmaxf(e0,e1);
                for(int o=16;o;o>>=1) m=fmaxf(m,__shfl_xor_sync(0xffffffffu,m,o));
                float x0=expf(e0-m), x1=expf(e1-m);
                float s=x0+x1;
                for(int o=16;o;o>>=1) s+=__shfl_xor_sync(0xffffffffu,s,o);
                salpha[lane]=x0/s; salpha[lane+32]=x1/s;
            }
            __syncthreads();
            for(int j=tid;j<2048;j+=256){
                float a=0.f;
                const bf16* eh = g_ench + (size_t)b*64*2048 + j;
                #pragma unroll 4
                for(int tt=0;tt<64;tt++) a += salpha[tt]*__bfloat162float(eh[(size_t)tt*2048]);
                g_combin[(size_t)b*3072 + j] = __float2bfloat16(a);
            }
        }
        gridBar(64, myGen);
        // ---- phase 3
        {
            float acc3[2][4];
            #pragma unroll
            for(int i=0;i<2;i++) for(int j=0;j<4;j++) acc3[i][j]=0.f;
            auto loadT2 = [&](int it, int buf){
                bf16* Av = dsm + buf*10880;
                bf16* Bv = Av + 8704;
                #pragma unroll
                for(int i=tid;i<1024;i+=256){ int r=i>>4, c=(i&15)*8;
                    cpasync16(&Av[r*KST+c], g_combin + (size_t)r*3072 + it*128 + c); }
                { int i=tid; if(i<256){ int r=i>>4, c=(i&15)*8;
                    cpasync16(&Bv[r*KST+c], g_Wcomb + (size_t)(nb*16+r)*3072 + it*128 + c); } }
                cpcommit();
            };
            loadT2(0,0);
            for(int it=0; it<24; it++){
                int cur=it&1;
                if(it<23){ loadT2(it+1, cur^1); cpwait<1>(); } else cpwait<0>();
                __syncthreads();
                u32 AsU = dsmU + cur*21760;
                u32 BsU = AsU + 17408;
                int kb = wg*64;
                #pragma unroll
                for(int kk=0;kk<64;kk+=16){
                    u32 a[4], bb[4];
                    ldm_x4(a, AsU + ((w4*16+arow)*KST + kb+kk + acol)*2);
                    ldm_x4(bb, BsU + ((brow)*KST + kb+kk + bcol)*2);
                    mma16816(acc3[0], a, bb);
                    mma16816(acc3[1], a, bb+2);
                }
                __syncthreads();
            }
            float* ps = (float*)dsm;
            if(wg==1){
                #pragma unroll
                for(int nt=0;nt<2;nt++){
                    int r0=w4*16+g, c0=nt*8+tg*2;
                    ps[r0*20+c0]=acc3[nt][0]; ps[r0*20+c0+1]=acc3[nt][1];
                    ps[(r0+8)*20+c0]=acc3[nt][2]; ps[(r0+8)*20+c0+1]=acc3[nt][3];
                }
            }
            __syncthreads();
            if(wg==0){
                #pragma unroll
                for(int nt=0;nt<2;nt++){
                    int r0=w4*16+g, c0l=nt*8+tg*2;
                    int c0 = nb*16 + c0l;
                    float v0=tanhf(acc3[nt][0]+ps[r0*20+c0l]);
                    float v1=tanhf(acc3[nt][1]+ps[r0*20+c0l+1]);
                    float v2=tanhf(acc3[nt][2]+ps[(r0+8)*20+c0l]);
                    float v3=tanhf(acc3[nt][3]+ps[(r0+8)*20+c0l+1]);
                    bf16 b0=__float2bfloat16(v0), b1=__float2bfloat16(v1);
                    bf16 b2=__float2bfloat16(v2), b3=__float2bfloat16(v3);
                    g_outs[((size_t)t*B_ + r0)*H_ + c0]   = b0;
                    g_outs[((size_t)t*B_ + r0)*H_ + c0+1] = b1;
                    g_outs[((size_t)t*B_ + r0+8)*H_ + c0]   = b2;
                    g_outs[((size_t)t*B_ + r0+8)*H_ + c0+1] = b3;
                    g_acat[(size_t)r0*2048 + 1024 + c0]   = b0;
                    g_acat[(size_t)r0*2048 + 1024 + c0+1] = b1;
                    g_acat[(size_t)(r0+8)*2048 + 1024 + c0]   = b2;
                    g_acat[(size_t)(r0+8)*2048 + 1024 + c0+1] = b3;
                }
            }
        }
        gridBar(64, myGen);
    }
}

// ---------------- vocab (3-stage, single sync) ----------------
__global__ void __launch_bounds__(256) vocabKernel(const int* __restrict__ tgt)
{
    extern __shared__ __align__(16) bf16 vsm[];
    const int STG = 128*AS_;
    __shared__ float redm[4][2][2][8][2];
    __shared__ float reds[4][2][2][8][2];
    int tid=threadIdx.x, warp=tid>>5, lane=tid&31, g=lane>>2, tg=lane&3;
    int wr=warp>>1, wc=warp&1;
    LDM_SETUP();
    u32 vsmU = (u32)__cvta_generic_to_shared(vsm);
    int bm=blockIdx.y*128, bn=blockIdx.x*128, chunk=blockIdx.x;
    float acc[2][8][4];
    #pragma unroll
    for(int i=0;i<2;i++) for(int j=0;j<8;j++) for(int k=0;k<4;k++) acc[i][j][k]=0.f;

    auto ld = [&](int it, int s){
        bf16* As = vsm + s*2*STG; bf16* Bs = As + STG;
        #pragma unroll
        for(int i=tid;i<512;i+=256){ int r=i>>2, c=(i&3)*8;
            cpasync16(&As[r*AS_+c], g_outs + (size_t)(bm+r)*1024 + it*32 + c); }
        #pragma unroll
        for(int i=tid;i<512;i+=256){ int r=i>>2, c=(i&3)*8;
            cpasync16(&Bs[r*AS_+c], g_Wvoc + (size_t)(bn+r)*1024 + it*32 + c); }
        cpcommit();
    };
    ld(0,0); ld(1,1);
    for(int it=0; it<32; it++){
        if(it<31) cpwait<1>(); else cpwait<0>();
        __syncthreads();
        if(it+2<32) ld(it+2, (it+2)%3);
        u32 AsU = vsmU + (it%3)*2*STG*2; u32 BsU = AsU + STG*2;
        #pragma unroll
        for(int kk=0;kk<32;kk+=16){
            u32 a[2][4], b[8][2];
            #pragma unroll
            for(int mi=0;mi<2;mi++)
                ldm_x4(a[mi], AsU + ((wr*32+mi*16+arow)*AS_ + kk + acol)*2);
            #pragma unroll
            for(int nj=0;nj<4;nj++)
                ldm_x4(&b[nj*2][0], BsU + ((wc*64+nj*16+brow)*AS_ + kk + bcol)*2);
            #pragma unroll
            for(int mi=0;mi<2;mi++)
                #pragma unroll
                for(int ni=0;ni<8;ni++)
                    mma16816(acc[mi][ni], a[mi], b[ni]);
        }
    }
    __syncthreads();
    #pragma unroll
    for(int mi=0;mi<2;mi++) for(int h=0;h<2;h++){
        float m=-1e30f;
        #pragma unroll
        for(int ni=0;ni<8;ni++) m=fmaxf(m, fmaxf(acc[mi][ni][h*2], acc[mi][ni][h*2+1]));
        m=fmaxf(m, __shfl_xor_sync(0xffffffffu,m,1));
        m=fmaxf(m, __shfl_xor_sync(0xffffffffu,m,2));
        if(tg==0) redm[wr][mi][h][g][wc]=m;
    }
    __syncthreads();
    #pragma unroll
    for(int mi=0;mi<2;mi++) for(int h=0;h<2;h++){
        float M=fmaxf(redm[wr][mi][h][g][0], redm[wr][mi][h][g][1]);
        float s=0.f;
        #pragma unroll
        for(int ni=0;ni<8;ni++){
            s+=expf(acc[mi][ni][h*2]-M);
            s+=expf(acc[mi][ni][h*2+1]-M);
        }
        s+=__shfl_xor_sync(0xffffffffu,s,1);
        s+=__shfl_xor_sync(0xffffffffu,s,2);
        if(tg==0) reds[wr][mi][h][g][wc]=s;
    }
    __syncthreads();
    if(wc==0 && tg==0){
        #pragma unroll
        for(int mi=0;mi<2;mi++) for(int h=0;h<2;h++){
            int grow = bm + wr*32 + mi*16 + h*8 + g;
            if(grow < TD_*B_){
                float M=fmaxf(redm[wr][mi][h][g][0], redm[wr][mi][h][g][1]);
                float S=reds[wr][mi][h][g][0]+reds[wr][mi][h][g][1];
                g_pmax[(size_t)grow*NCH+chunk]=M;
                g_psum[(size_t)grow*NCH+chunk]=S;
            }
        }
    }
    #pragma unroll
    for(int mi=0;mi<2;mi++) for(int h=0;h<2;h++){
        int grow = bm + wr*32 + mi*16 + h*8 + g;
        if(grow < TD_*B_){
            int gi = tgt[grow + 64];
            #pragma unroll
            for(int ni=0;ni<8;ni++){
                int c0 = bn + wc*64 + ni*8 + tg*2;
                if(c0==gi)   g_pgold[grow]=acc[mi][ni][h*2];
                if(c0+1==gi) g_pgold[grow]=acc[mi][ni][h*2+1];
            }
        }
    }
}

// ---------------- small kernels ----------------
__global__ void hcatK(){
    int i=blockIdx.x*blockDim.x+threadIdx.x;
    if(i>=B_*2048) return;
    int b=i>>11, j=i&2047;
    float hv = (j<1024)? g_hf[b*1024+j] : g_hb[b*1024+j-1024];
    float cv = (j<1024)? g_cf[b*1024+j] : g_cb[b*1024+j-1024];
    g_hcat[i]=__float2bfloat16(hv);
    g_ccat[i]=__float2bfloat16(cv);
}
__global__ void finalReduceK(const int* __restrict__ tgt, float* __restrict__ out){
    __shared__ float sm[64];
    int b=blockIdx.x, t=threadIdx.x;
    float v=0.f;
    if(t<TD_){
        int row=t*64+b;
        float m=-1e30f;
        for(int j=0;j<NCH;j++) m=fmaxf(m, g_pmax[(size_t)row*NCH+j]);
        float s=0.f;
        for(int j=0;j<NCH;j++) s+=g_psum[(size_t)row*NCH+j]*expf(g_pmax[(size_t)row*NCH+j]-m);
        float gold = g_pgold[row] - (m + logf(s));
        v = (tgt[row+64]!=0)? gold : 0.f;
    }
    sm[t]=v; __syncthreads();
    for(int o=32;o;o>>=1){ if(t<o) sm[t]+=sm[t+o]; __syncthreads(); }
    if(t==0) out[b]=sm[0];
}

// ---------------- host ----------------
template<typename Ty, size_t N> static Ty* gp(Ty (&arr)[N]){
    void* p=nullptr; cudaGetSymbolAddress(&p, arr); return (Ty*)p;
}
#define ENC_SMEM ((64*EST + 2*64*AST)*2)
#define G128_SMEM (3*2*128*AS_*2)
#define DEC_SMEM (2*34816)

extern "C" void kernel_launch(void* const* d_in, const int* in_sizes, int n_in,
                              void* d_out, int out_size){
    (void)in_sizes; (void)n_in; (void)out_size;
    const int* src  = (const int*)d_in[0];
    const int* tgt  = (const int*)d_in[1];
    const int* lens = (const int*)d_in[2];
    const float* src_embed=(const float*)d_in[3];
    const float* dst_embed=(const float*)d_in[4];
    const float* WihF=(const float*)d_in[5];
    const float* WhhF=(const float*)d_in[6];
    const float* bihF=(const float*)d_in[7];
    const float* bhhF=(const float*)d_in[8];
    const float* WihB=(const float*)d_in[9];
    const float* WhhB=(const float*)d_in[10];
    const float* bihB=(const float*)d_in[11];
    const float* bhhB=(const float*)d_in[12];
    const float* Wihd=(const float*)d_in[13];
    const float* Whhd=(const float*)d_in[14];
    const float* bihd=(const float*)d_in[15];
    const float* bhhd=(const float*)d_in[16];
    const float* Whp =(const float*)d_in[17];
    const float* Wcp =(const float*)d_in[18];
    const float* Watt=(const float*)d_in[19];
    const float* Wcmb=(const float*)d_in[20];
    const float* Wvoc=(const float*)d_in[21];
    float* out=(float*)d_out;

    bf16 *sWihF=gp(g_WihF), *sWihB=gp(g_WihB);
    bf16 *sWihd=gp(g_Wihd);
    bf16 *sWatt=gp(g_Watt);
    float *sbF=gp(g_bEncF), *sbB=gp(g_bEncB), *sbD=gp(g_bDec);
    bf16 *sXg=gp(g_Xg), *sYg=gp(g_Yg);
    float *sGxF=gp(g_GxF), *sGxB=gp(g_GxB), *sGy=gp(g_Gy);
    bf16 *sench=gp(g_ench), *sencp=gp(g_encproj);
    bf16 *shcat=gp(g_hcat), *sccat=gp(g_ccat);
    float *scdec=gp(g_cdec);
    bf16 *sacat=gp(g_acat);

    static int attrSet = 0;
    if(!attrSet){
        cudaFuncSetAttribute(encPersist, cudaFuncAttributeMaxDynamicSharedMemorySize, ENC_SMEM);
        cudaFuncSetAttribute(gemm128, cudaFuncAttributeMaxDynamicSharedMemorySize, G128_SMEM);
        cudaFuncSetAttribute(vocabKernel, cudaFuncAttributeMaxDynamicSharedMemorySize, G128_SMEM);
        cudaFuncSetAttribute(decPersist, cudaFuncAttributeMaxDynamicSharedMemorySize, DEC_SMEM);
        attrSet = 1;
    }

    prepK<<<2048,256>>>(WihF,WhhF,WihB,WhhB,Wihd,Whhd,Whp,Wcp,Watt,Wcmb,Wvoc,
                        bihF,bhhF,bihB,bhhB,bihd,bhhd,
                        src, tgt, src_embed, dst_embed);
    gemm128<<<dim3(32,32),256,G128_SMEM>>>(sXg,E_, sWihF,E_, sGxF,G_,0, 1, sbF, E_);
    gemm128<<<dim3(32,32),256,G128_SMEM>>>(sXg,E_, sWihB,E_, sGxB,G_,0, 1, sbB, E_);
    gemm128<<<dim3(32,32),256,G128_SMEM>>>(sYg,E_, sWihd,1536, sGy,G_,0, 1, sbD, E_);
    barResetK<<<1,1>>>();
    encPersist<<<128,256,ENC_SMEM>>>(lens);
    hcatK<<<512,256>>>();
    gemm64<<<dim3(16,1),128>>>(shcat,2048, gp(g_Whp),2048, (float*)sacat,2048,1, 2048);
    gemm64<<<dim3(16,1),128>>>(sccat,2048, gp(g_Wcp),2048, scdec,H_,0, 2048);
    gemm128<<<dim3(8,32),256,G128_SMEM>>>(sench,2048, sWatt,2048, (float*)sencp,H_,1, 0, nullptr, 2048);
    barResetK<<<1,1>>>();
    decPersist<<<64,256,DEC_SMEM>>>(lens);
    vocabKernel<<<dim3(NCH, 32),256,G128_SMEM>>>(tgt);
    finalReduceK<<<64,64>>>(tgt, out);
}

// round 17
// speedup vs baseline: 1.1407x; 1.1407x over previous
#include <cuda_runtime.h>
#include <cuda_bf16.h>

typedef __nv_bfloat16 bf16;
typedef unsigned int u32;

#define E_ 512
#define H_ 1024
#define B_ 64
#define T_ 64
#define TD_ 63
#define V_ 32000
#define G_ 4096
#define NCH 250
#define AS_ 40
#define AST 72
#define EST 1048
#define SGS 68
#define KST 136

// ---------------- device scratch ----------------
__device__ bf16 g_WihF[G_*E_];
__device__ bf16 g_WhhF[G_*H_];
__device__ bf16 g_WihB[G_*E_];
__device__ bf16 g_WhhB[G_*H_];
__device__ bf16 g_Wihd[G_*(E_+H_)];
__device__ bf16 g_Wdec[G_*2048];
__device__ bf16 g_Whp[H_*2048];
__device__ bf16 g_Wcp[H_*2048];
__device__ bf16 g_Watt[H_*2048];
__device__ bf16 g_Wcomb[H_*3072];
__device__ bf16 g_Wvoc[V_*H_];
__device__ float g_bEncF[G_], g_bEncB[G_], g_bDec[G_];
__device__ bf16 g_Xg[T_*B_*E_];
__device__ bf16 g_Yg[4096*E_];
__device__ float g_GxF[T_*B_*G_];
__device__ float g_GxB[T_*B_*G_];
__device__ float g_Gy[4096*G_];
__device__ float g_hf[B_*H_], g_cf[B_*H_], g_hb[B_*H_], g_cb[B_*H_];
__device__ bf16 g_hfh[B_*H_], g_hbh[B_*H_];
__device__ bf16 g_ench[B_*T_*2048];
__device__ bf16 g_encproj[B_*T_*H_];
__device__ bf16 g_hcat[B_*2048], g_ccat[B_*2048];
__device__ float g_cdec[B_*H_];
__device__ bf16 g_acat[B_*2048];
__device__ float g_gates[B_*G_];
__device__ bf16 g_combin[B_*3072];
__device__ bf16 g_outs[4096*H_];
__device__ float g_pmax[TD_*B_*NCH], g_psum[TD_*B_*NCH], g_pgold[TD_*B_];
__device__ unsigned int g_barCnt;
__device__ unsigned int g_barGen;

// ---------------- helpers ----------------
__device__ __forceinline__ float sigf(float x){ return 1.f/(1.f+expf(-x)); }

__device__ __forceinline__ void mma16816(float* c, const u32* a, const u32* b){
    asm volatile("mma.sync.aligned.m16n8k16.row.col.f32.bf16.bf16.f32 "
        "{%0,%1,%2,%3},{%4,%5,%6,%7},{%8,%9},{%0,%1,%2,%3};\n"
        : "+f"(c[0]),"+f"(c[1]),"+f"(c[2]),"+f"(c[3])
        : "r"(a[0]),"r"(a[1]),"r"(a[2]),"r"(a[3]),"r"(b[0]),"r"(b[1]));
}
__device__ __forceinline__ void ldm_x4(u32* r, u32 addr){
    asm volatile("ldmatrix.sync.aligned.m8n8.x4.shared.b16 {%0,%1,%2,%3}, [%4];\n"
        : "=r"(r[0]),"=r"(r[1]),"=r"(r[2]),"=r"(r[3]) : "r"(addr));
}
__device__ __forceinline__ void ldm_x2(u32* r, u32 addr){
    asm volatile("ldmatrix.sync.aligned.m8n8.x2.shared.b16 {%0,%1}, [%2];\n"
        : "=r"(r[0]),"=r"(r[1]) : "r"(addr));
}
__device__ __forceinline__ void cpasync16(void* sdst, const void* gsrc){
    u32 s = (u32)__cvta_generic_to_shared(sdst);
    asm volatile("cp.async.ca.shared.global [%0], [%1], 16;\n" :: "r"(s), "l"(gsrc));
}
__device__ __forceinline__ void cpcommit(){ asm volatile("cp.async.commit_group;\n"); }
template<int N> __device__ __forceinline__ void cpwait(){ asm volatile("cp.async.wait_group %0;\n"::"n"(N)); }

__global__ void barResetK(){ g_barCnt=0; g_barGen=0; }

__device__ __forceinline__ void gridBar(unsigned int nCTA, unsigned int &myGen){
    __syncthreads();
    myGen++;
    if(threadIdx.x==0){
        __threadfence();
        unsigned int a = atomicAdd(&g_barCnt, 1);
        if(a == nCTA-1){
            g_barCnt = 0;
            __threadfence();
            atomicExch(&g_barGen, myGen);
        } else {
            while(true){
                unsigned int v = *((volatile unsigned int*)&g_barGen);
                if(v >= myGen) break;
                __nanosleep(32);
            }
            __threadfence();
        }
    }
    __syncthreads();
}

#define LDM_SETUP() \
    u32 arow = (lane&7) + ((lane>>3)&1)*8; \
    u32 acol = (lane>>4)*8; \
    u32 brow = (lane&7) + ((lane>>4)&1)*8; \
    u32 bcol = ((lane>>3)&1)*8;

// ---------------- prep megakernel ----------------
__device__ __forceinline__ u32 pack2(float x, float y){
    __nv_bfloat162 h = __floats2bfloat162_rn(x, y);
    return *(u32*)&h;
}
__global__ void prepK(
    const float* __restrict__ WihF, const float* __restrict__ WhhF,
    const float* __restrict__ WihB, const float* __restrict__ WhhB,
    const float* __restrict__ Wihd, const float* __restrict__ Whhd,
    const float* __restrict__ Whp,  const float* __restrict__ Wcp,
    const float* __restrict__ Watt, const float* __restrict__ Wcmb,
    const float* __restrict__ Wvoc,
    const float* __restrict__ bihF, const float* __restrict__ bhhF,
    const float* __restrict__ bihB, const float* __restrict__ bhhB,
    const float* __restrict__ bihd, const float* __restrict__ bhhd,
    const int* __restrict__ srcTok, const int* __restrict__ tgtTok,
    const float* __restrict__ srcEmb, const float* __restrict__ dstEmb)
{
    int stride = gridDim.x*blockDim.x;
    int t0 = blockIdx.x*blockDim.x + threadIdx.x;
    auto cvt4 = [&](const float* s, bf16* d, int n){
        const float4* s4 = (const float4*)s;
        uint2* d4 = (uint2*)d;
        int n4 = n>>2;
        for(int i=t0;i<n4;i+=stride){
            float4 v = s4[i];
            uint2 o; o.x = pack2(v.x,v.y); o.y = pack2(v.z,v.w);
            d4[i] = o;
        }
    };
    cvt4(WihF, g_WihF, G_*E_);
    cvt4(WihB, g_WihB, G_*E_);
    cvt4(Wihd, g_Wihd, G_*1536);
    cvt4(Whp,  g_Whp,  H_*2048);
    cvt4(Wcp,  g_Wcp,  H_*2048);
    cvt4(Watt, g_Watt, H_*2048);
    cvt4(Wcmb, g_Wcomb,H_*3072);
    cvt4(Wvoc, g_Wvoc, V_*H_);
    for(int i=t0;i<(G_*H_)>>2;i+=stride){
        int p=i>>8, k4=i&255;
        int nb=p>>6, c=p&63, q=c>>4, jj=c&15;
        float4 v = *(const float4*)(WhhF + (size_t)(q*1024+nb*16+jj)*1024 + k4*4);
        uint2 o; o.x=pack2(v.x,v.y); o.y=pack2(v.z,v.w);
        *(uint2*)(g_WhhF + (size_t)p*1024 + k4*4) = o;
    }
    for(int i=t0;i<(G_*H_)>>2;i+=stride){
        int p=i>>8, k4=i&255;
        int nb=p>>6, c=p&63, q=c>>4, jj=c&15;
        float4 v = *(const float4*)(WhhB + (size_t)(q*1024+nb*16+jj)*1024 + k4*4);
        uint2 o; o.x=pack2(v.x,v.y); o.y=pack2(v.z,v.w);
        *(uint2*)(g_WhhB + (size_t)p*1024 + k4*4) = o;
    }
    for(int i=t0;i<(G_*2048)>>2;i+=stride){
        int n=i>>9, k=(i&511)*4;
        const float* s = (k<1024)? (Whhd + (size_t)n*1024 + k)
                                 : (Wihd + (size_t)n*1536 + 512 + (k-1024));
        float4 v = *(const float4*)s;
        uint2 o; o.x=pack2(v.x,v.y); o.y=pack2(v.z,v.w);
        *(uint2*)(g_Wdec + (size_t)n*2048 + k) = o;
    }
    for(int i=t0;i<(T_*B_*E_)>>2;i+=stride){
        int r=i>>7, c4=i&127;
        float4 v = *(const float4*)(srcEmb + (size_t)srcTok[r]*E_ + c4*4);
        uint2 o; o.x=pack2(v.x,v.y); o.y=pack2(v.z,v.w);
        *(uint2*)(g_Xg + (size_t)r*E_ + c4*4) = o;
    }
    for(int i=t0;i<(TD_*B_*E_)>>2;i+=stride){
        int r=i>>7, c4=i&127;
        float4 v = *(const float4*)(dstEmb + (size_t)tgtTok[r]*E_ + c4*4);
        uint2 o; o.x=pack2(v.x,v.y); o.y=pack2(v.z,v.w);
        *(uint2*)(g_Yg + (size_t)r*E_ + c4*4) = o;
    }
    for(int i=t0;i<G_;i+=stride){
        g_bEncF[i]=bihF[i]+bhhF[i];
        g_bEncB[i]=bihB[i]+bhhB[i];
        g_bDec[i]=bihd[i]+bhhd[i];
    }
    for(int i=t0;i<B_*H_;i+=stride){
        g_hf[i]=0.f; g_cf[i]=0.f; g_hb[i]=0.f; g_cb[i]=0.f;
        bf16 z=__float2bfloat16(0.f);
        g_hfh[i]=z; g_hbh[i]=z;
        g_acat[(i>>10)*2048 + 1024 + (i&1023)] = z;
    }
    for(int i=t0;i<64*E_;i+=stride) g_Yg[4032*E_ + i]=__float2bfloat16(0.f);
    for(int i=t0;i<64*H_;i+=stride) g_outs[(size_t)4032*H_ + i]=__float2bfloat16(0.f);
}

// ---------------- gemm128: 3-stage, single sync ----------------
__global__ void __launch_bounds__(256) gemm128(
    const bf16* __restrict__ A, int lda,
    const bf16* __restrict__ Bw, int ldb,
    float* C, int ldc, int outBf16,
    int dmode, const float* __restrict__ D, int K)
{
    extern __shared__ __align__(16) bf16 gsm[];
    const int STG = 128*AS_;
    int tid=threadIdx.x, warp=tid>>5, lane=tid&31, g=lane>>2, tg=lane&3;
    int wr=warp>>1, wc=warp&1;
    LDM_SETUP();
    u32 gsmU = (u32)__cvta_generic_to_shared(gsm);
    int bm=blockIdx.y*128, bn=blockIdx.x*128;
    float acc[2][8][4];
    #pragma unroll
    for(int i=0;i<2;i++) for(int j=0;j<8;j++) for(int k=0;k<4;k++) acc[i][j][k]=0.f;
    int nIt = K>>5;
    auto ld = [&](int it, int s){
        bf16* As = gsm + s*2*STG; bf16* Bs = As + STG;
        #pragma unroll
        for(int i=tid;i<512;i+=256){ int r=i>>2, c=(i&3)*8;
            cpasync16(&As[r*AS_+c], A + (size_t)(bm+r)*lda + it*32 + c); }
        #pragma unroll
        for(int i=tid;i<512;i+=256){ int r=i>>2, c=(i&3)*8;
            cpasync16(&Bs[r*AS_+c], Bw + (size_t)(bn+r)*ldb + it*32 + c); }
        cpcommit();
    };
    ld(0,0); ld(1,1);
    for(int it=0; it<nIt; it++){
        if(it+1<nIt) cpwait<1>(); else cpwait<0>();
        __syncthreads();
        if(it+2<nIt) ld(it+2, (it+2)%3);
        u32 AsU = gsmU + (it%3)*2*STG*2; u32 BsU = AsU + STG*2;
        #pragma unroll
        for(int kk=0;kk<32;kk+=16){
            u32 a[2][4], b[8][2];
            #pragma unroll
            for(int mi=0;mi<2;mi++)
                ldm_x4(a[mi], AsU + ((wr*32+mi*16+arow)*AS_ + kk + acol)*2);
            #pragma unroll
            for(int nj=0;nj<4;nj++)
                ldm_x4(&b[nj*2][0], BsU + ((wc*64+nj*16+brow)*AS_ + kk + bcol)*2);
            #pragma unroll
            for(int mi=0;mi<2;mi++)
                #pragma unroll
                for(int ni=0;ni<8;ni++)
                    mma16816(acc[mi][ni], a[mi], b[ni]);
        }
    }
    #pragma unroll
    for(int mi=0;mi<2;mi++){
        #pragma unroll
        for(int ni=0;ni<8;ni++){
            int r0 = bm + wr*32 + mi*16 + g;
            int c0 = bn + wc*64 + ni*8 + tg*2;
            float v0=acc[mi][ni][0], v1=acc[mi][ni][1], v2=acc[mi][ni][2], v3=acc[mi][ni][3];
            if(dmode==1){ v0+=D[c0]; v1+=D[c0+1]; v2+=D[c0]; v3+=D[c0+1]; }
            if(outBf16){
                bf16* Cb=(bf16*)C;
                Cb[(size_t)r0*ldc+c0]=__float2bfloat16(v0);
                Cb[(size_t)r0*ldc+c0+1]=__float2bfloat16(v1);
                Cb[(size_t)(r0+8)*ldc+c0]=__float2bfloat16(v2);
                Cb[(size_t)(r0+8)*ldc+c0+1]=__float2bfloat16(v3);
            } else {
                C[(size_t)r0*ldc+c0]=v0; C[(size_t)r0*ldc+c0+1]=v1;
                C[(size_t)(r0+8)*ldc+c0]=v2; C[(size_t)(r0+8)*ldc+c0+1]=v3;
            }
        }
    }
}

// ---------------- gemm64 (R9 pattern) ----------------
__global__ void __launch_bounds__(128) gemm64(
    const bf16* __restrict__ A, int lda,
    const bf16* __restrict__ Bw, int ldb,
    float* C, int ldc, int outBf16, int K)
{
    __shared__ __align__(16) bf16 As[2][64*AS_];
    __shared__ __align__(16) bf16 Bs[2][64*AS_];
    int tid=threadIdx.x, warp=tid>>5, lane=tid&31, g=lane>>2, tg=lane&3;
    int wr=warp>>1, wc=warp&1;
    LDM_SETUP();
    u32 AsU0 = (u32)__cvta_generic_to_shared(&As[0][0]);
    u32 BsU0 = (u32)__cvta_generic_to_shared(&Bs[0][0]);
    int bm=blockIdx.y*64, bn=blockIdx.x*64;
    float acc[2][4][4];
    #pragma unroll
    for(int i=0;i<2;i++) for(int j=0;j<4;j++) for(int k=0;k<4;k++) acc[i][j][k]=0.f;
    int nIt = K>>5;
    auto loadTile = [&](int it, int buf){
        #pragma unroll
        for(int i=tid;i<256;i+=128){ int r=i>>2, c=(i&3)*8;
            cpasync16(&As[buf][r*AS_+c], A + (size_t)(bm+r)*lda + it*32 + c); }
        #pragma unroll
        for(int i=tid;i<256;i+=128){ int r=i>>2, c=(i&3)*8;
            cpasync16(&Bs[buf][r*AS_+c], Bw + (size_t)(bn+r)*ldb + it*32 + c); }
        cpcommit();
    };
    loadTile(0,0);
    for(int it=0; it<nIt; it++){
        int cur=it&1;
        if(it+1<nIt){ loadTile(it+1, cur^1); cpwait<1>(); } else cpwait<0>();
        __syncthreads();
        u32 AsU = AsU0 + cur*64*AS_*2;
        u32 BsU = BsU0 + cur*64*AS_*2;
        #pragma unroll
        for(int kk=0;kk<32;kk+=16){
            u32 a[2][4], b[4][2];
            #pragma unroll
            for(int mi=0;mi<2;mi++)
                ldm_x4(a[mi], AsU + ((wr*32+mi*16+arow)*AS_ + kk + acol)*2);
            #pragma unroll
            for(int nj=0;nj<2;nj++)
                ldm_x4(&b[nj*2][0], BsU + ((wc*32+nj*16+brow)*AS_ + kk + bcol)*2);
            #pragma unroll
            for(int mi=0;mi<2;mi++)
                #pragma unroll
                for(int ni=0;ni<4;ni++)
                    mma16816(acc[mi][ni], a[mi], b[ni]);
        }
        __syncthreads();
    }
    #pragma unroll
    for(int mi=0;mi<2;mi++){
        #pragma unroll
        for(int ni=0;ni<4;ni++){
            int r0 = bm + wr*32 + mi*16 + g;
            int c0 = bn + wc*32 + ni*8 + tg*2;
            if(outBf16){
                bf16* Cb=(bf16*)C;
                Cb[(size_t)r0*ldc+c0]=__float2bfloat16(acc[mi][ni][0]);
                Cb[(size_t)r0*ldc+c0+1]=__float2bfloat16(acc[mi][ni][1]);
                Cb[(size_t)(r0+8)*ldc+c0]=__float2bfloat16(acc[mi][ni][2]);
                Cb[(size_t)(r0+8)*ldc+c0+1]=__float2bfloat16(acc[mi][ni][3]);
            } else {
                C[(size_t)r0*ldc+c0]=acc[mi][ni][0]; C[(size_t)r0*ldc+c0+1]=acc[mi][ni][1];
                C[(size_t)(r0+8)*ldc+c0]=acc[mi][ni][2]; C[(size_t)(r0+8)*ldc+c0+1]=acc[mi][ni][3];
            }
        }
    }
}

// ---------------- persistent encoder (R9 pattern) ----------------
__global__ void __launch_bounds__(256) encPersist(const int* __restrict__ lens){
    extern __shared__ __align__(16) bf16 esm[];
    bf16* Ws  = esm;
    bf16* As0 = esm + 64*EST;
    bf16* As1 = As0 + 64*AST;
    float* sgate = (float*)As0;
    __shared__ int slen[64];
    int tid=threadIdx.x, warp=tid>>5, lane=tid&31, g=lane>>2, tg=lane&3;
    int wr=warp>>1, wc=warp&1;
    LDM_SETUP();
    u32 WsU  = (u32)__cvta_generic_to_shared(Ws);
    u32 As0U = (u32)__cvta_generic_to_shared(As0);
    u32 As1U = (u32)__cvta_generic_to_shared(As1);
    int dir = blockIdx.x>>6, nb = blockIdx.x&63;
    const bf16* W = (dir? g_WhhB : g_WhhF) + (size_t)nb*64*1024;
    const bf16* hsrc = dir? g_hbh : g_hfh;
    const float* Gx = dir? g_GxB : g_GxF;
    float* hs = dir ? g_hb : g_hf;
    float* cs = dir ? g_cb : g_cf;
    bf16* hh = dir ? g_hbh : g_hfh;
    unsigned int myGen = 0;

    if(tid<64) slen[tid]=lens[tid];
    for(int i=tid;i<8192;i+=256){
        int r=i>>7, c=(i&127)*8;
        *(uint4*)&Ws[r*EST+c] = *(const uint4*)(W + r*1024 + c);
    }
    __syncthreads();

    for(int t=0;t<64;t++){
        int time = dir? (63-t) : t;
        float acc[4][4];
        #pragma unroll
        for(int i=0;i<4;i++) for(int j=0;j<4;j++) acc[i][j]=0.f;

        #pragma unroll
        for(int i=tid;i<512;i+=256){ int r=i>>3, c=(i&7)*8;
            cpasync16(&As0[r*AST+c], hsrc + r*1024 + c); }
        cpcommit();

        #pragma unroll
        for(int it=0; it<16; it++){
            u32 curU = (it&1)? As1U : As0U;
            bf16* nxt = (it&1)? As0 : As1;
            if(it<15){
                #pragma unroll
                for(int i=tid;i<512;i+=256){ int r=i>>3, c=(i&7)*8;
                    cpasync16(&nxt[r*AST+c], hsrc + r*1024 + (it+1)*64 + c); }
                cpcommit();
                cpwait<1>();
            } else cpwait<0>();
            __syncthreads();
            #pragma unroll
            for(int kk=0;kk<64;kk+=16){
                u32 a[4], b[4][2];
                ldm_x4(a, curU + ((wr*16+arow)*AST + kk + acol)*2);
                #pragma unroll
                for(int nj=0;nj<2;nj++)
                    ldm_x4(&b[nj*2][0], WsU + ((wc*32+nj*16+brow)*EST + it*64 + kk + bcol)*2);
                #pragma unroll
                for(int ni=0;ni<4;ni++) mma16816(acc[ni], a, b[ni]);
            }
            __syncthreads();
        }
        #pragma unroll
        for(int ni=0;ni<4;ni++){
            int c  = wc*32 + ni*8 + tg*2;
            int oc = (c>>4)*1024 + nb*16 + (c&15);
            int r0 = wr*16 + g;
            const float* gx0 = Gx + ((size_t)time*B_ + r0)*G_ + oc;
            const float* gx1 = gx0 + 8*G_;
            sgate[r0*SGS + c]       = acc[ni][0] + gx0[0];
            sgate[r0*SGS + c + 1]   = acc[ni][1] + gx0[1];
            sgate[(r0+8)*SGS + c]   = acc[ni][2] + gx1[0];
            sgate[(r0+8)*SGS + c+1] = acc[ni][3] + gx1[1];
        }
        __syncthreads();
        #pragma unroll
        for(int idx=tid; idx<1024; idx+=256){
            int b=idx>>4, jj=idx&15;
            float gi=sgate[b*SGS+jj], gf=sgate[b*SGS+16+jj];
            float gc=sgate[b*SGS+32+jj], go=sgate[b*SGS+48+jj];
            int r = b*1024 + nb*16 + jj;
            float c=cs[r], h=hs[r];
            float c2 = sigf(gf)*c + sigf(gi)*tanhf(gc);
            float h2 = sigf(go)*tanhf(c2);
            bool m = time < slen[b];
            float hn = m?h2:h, cn = m?c2:c;
            hs[r]=hn; cs[r]=cn; hh[r]=__float2bfloat16(hn);
            g_ench[(size_t)(b*64+time)*2048 + dir*1024 + nb*16+jj] = __float2bfloat16(m?h2:0.f);
        }
        gridBar(128, myGen);
    }
}

// ---------------- persistent decoder (R9 pattern + vectorized phase 2) ----------------
__global__ void __launch_bounds__(256) decPersist(const int* __restrict__ lens){
    extern __shared__ __align__(16) bf16 dsm[];
    __shared__ float h2s[1024];
    __shared__ float salpha[64];
    __shared__ float cstate[1024];
    int tid=threadIdx.x, warp=tid>>5, lane=tid&31, g=lane>>2, tg=lane&3;
    int wg = warp>>2, w4 = warp&3, wr2 = w4>>1, wc2 = w4&1;
    LDM_SETUP();
    u32 dsmU = (u32)__cvta_generic_to_shared(dsm);
    int nb = blockIdx.x;
    int b  = blockIdx.x;
    unsigned int myGen = 0;

    for(int j=tid;j<1024;j+=256) cstate[j]=g_cdec[b*1024+j];
    __syncthreads();

    for(int t=0;t<TD_;t++){
        // ---- phase 1
        {
            float acc[2][4][4];
            #pragma unroll
            for(int i=0;i<2;i++) for(int j=0;j<4;j++) for(int k=0;k<4;k++) acc[i][j][k]=0.f;
            auto loadT = [&](int it, int buf){
                bf16* Av = dsm + buf*17408;
                bf16* Bv = Av + 8704;
                #pragma unroll
                for(int i=tid;i<1024;i+=256){ int r=i>>4, c=(i&15)*8;
                    cpasync16(&Av[r*KST+c], g_acat + (size_t)r*2048 + it*128 + c); }
                #pragma unroll
                for(int i=tid;i<1024;i+=256){ int r=i>>4, c=(i&15)*8;
                    cpasync16(&Bv[r*KST+c], g_Wdec + (size_t)(nb*64+r)*2048 + it*128 + c); }
                cpcommit();
            };
            loadT(0,0);
            for(int it=0; it<16; it++){
                int cur=it&1;
                if(it<15){ loadT(it+1, cur^1); cpwait<1>(); } else cpwait<0>();
                __syncthreads();
                u32 AsU = dsmU + cur*34816;
                u32 BsU = AsU + 17408;
                int kb = wg*64;
                #pragma unroll
                for(int kk=0;kk<64;kk+=16){
                    u32 a[2][4], bb[4][2];
                    #pragma unroll
                    for(int mi=0;mi<2;mi++)
                        ldm_x4(a[mi], AsU + ((wr2*32+mi*16+arow)*KST + kb+kk + acol)*2);
                    #pragma unroll
                    for(int nj=0;nj<2;nj++)
                        ldm_x4(&bb[nj*2][0], BsU + ((wc2*32+nj*16+brow)*KST + kb+kk + bcol)*2);
                    #pragma unroll
                    for(int mi=0;mi<2;mi++)
                        #pragma unroll
                        for(int ni=0;ni<4;ni++)
                            mma16816(acc[mi][ni], a[mi], bb[ni]);
                }
                __syncthreads();
            }
            float* ps = (float*)dsm;
            if(wg==1){
                #pragma unroll
                for(int mi=0;mi<2;mi++)
                #pragma unroll
                for(int ni=0;ni<4;ni++){
                    int r0=wr2*32+mi*16+g, c0=wc2*32+ni*8+tg*2;
                    ps[r0*68+c0]  =acc[mi][ni][0]; ps[r0*68+c0+1]  =acc[mi][ni][1];
                    ps[(r0+8)*68+c0]=acc[mi][ni][2]; ps[(r0+8)*68+c0+1]=acc[mi][ni][3];
                }
            }
            __syncthreads();
            if(wg==0){
                #pragma unroll
                for(int mi=0;mi<2;mi++)
                #pragma unroll
                for(int ni=0;ni<4;ni++){
                    int r0=wr2*32+mi*16+g, c0=wc2*32+ni*8+tg*2;
                    int c = nb*64 + c0;
                    const float* gy0 = g_Gy + ((size_t)t*B_ + r0)*G_ + c;
                    const float* gy1 = gy0 + 8*G_;
                    float* gg0 = g_gates + (size_t)r0*G_ + c;
                    float* gg1 = gg0 + 8*G_;
                    gg0[0]=acc[mi][ni][0]+ps[r0*68+c0]+gy0[0];
                    gg0[1]=acc[mi][ni][1]+ps[r0*68+c0+1]+gy0[1];
                    gg1[0]=acc[mi][ni][2]+ps[(r0+8)*68+c0]+gy1[0];
                    gg1[1]=acc[mi][ni][3]+ps[(r0+8)*68+c0+1]+gy1[1];
                }
            }
        }
        gridBar(64, myGen);
        // ---- phase 2: cell + attention (vectorized bf16x2 loads)
        {
            const float* gg = g_gates + (size_t)b*G_;
            for(int j=tid;j<1024;j+=256){
                float gi=gg[j], gf=gg[1024+j], gc=gg[2048+j], go=gg[3072+j];
                float c = cstate[j];
                float c2 = sigf(gf)*c + sigf(gi)*tanhf(gc);
                float h2 = sigf(go)*tanhf(c2);
                cstate[j]=c2; h2s[j]=h2;
                bf16 hb=__float2bfloat16(h2);
                g_acat[(size_t)b*2048 + j] = hb;
                g_combin[(size_t)b*3072 + 2048 + j] = hb;
            }
            __syncthreads();
            int L = lens[b];
            for(int tt=warp; tt<64; tt+=8){
                const __nv_bfloat162* ep2 = (const __nv_bfloat162*)(g_encproj + (size_t)(b*64+tt)*1024);
                float s=0.f;
                for(int k=lane;k<512;k+=32){
                    __nv_bfloat162 v = ep2[k];
                    s += __bfloat162float(v.x)*h2s[2*k] + __bfloat162float(v.y)*h2s[2*k+1];
                }
                for(int o=16;o;o>>=1) s += __shfl_xor_sync(0xffffffffu,s,o);
                if(lane==0) salpha[tt] = (tt<L)? s : -1e30f;
            }
            __syncthreads();
            if(warp==0){
                float e0=salpha[lane], e1=salpha[lane+32];
                float m=fmaxf(e0,e1);
                for(int o=16;o;o>>=1) m=fmaxf(m,__shfl_xor_sync(0xffffffffu,m,o));
                float x0=expf(e0-m), x1=expf(e1-m);
                float s=x0+x1;
                for(int o=16;o;o>>=1) s+=__shfl_xor_sync(0xffffffffu,s,o);
                salpha[lane]=x0/s; salpha[lane+32]=x1/s;
            }
            __syncthreads();
            for(int jp=tid; jp<1024; jp+=256){
                float a0=0.f, a1=0.f;
                const __nv_bfloat162* eh2 = (const __nv_bfloat162*)(g_ench + (size_t)b*64*2048) + jp;
                #pragma unroll 4
                for(int tt=0;tt<64;tt++){
                    __nv_bfloat162 v = eh2[(size_t)tt*1024];
                    float al = salpha[tt];
                    a0 += al*__bfloat162float(v.x);
                    a1 += al*__bfloat162float(v.y);
                }
                g_combin[(size_t)b*3072 + 2*jp]   = __float2bfloat16(a0);
                g_combin[(size_t)b*3072 + 2*jp+1] = __float2bfloat16(a1);
            }
        }
        gridBar(64, myGen);
        // ---- phase 3
        {
            float acc3[2][4];
            #pragma unroll
            for(int i=0;i<2;i++) for(int j=0;j<4;j++) acc3[i][j]=0.f;
            auto loadT2 = [&](int it, int buf){
                bf16* Av = dsm + buf*10880;
                bf16* Bv = Av + 8704;
                #pragma unroll
                for(int i=tid;i<1024;i+=256){ int r=i>>4, c=(i&15)*8;
                    cpasync16(&Av[r*KST+c], g_combin + (size_t)r*3072 + it*128 + c); }
                { int i=tid; if(i<256){ int r=i>>4, c=(i&15)*8;
                    cpasync16(&Bv[r*KST+c], g_Wcomb + (size_t)(nb*16+r)*3072 + it*128 + c); } }
                cpcommit();
            };
            loadT2(0,0);
            for(int it=0; it<24; it++){
                int cur=it&1;
                if(it<23){ loadT2(it+1, cur^1); cpwait<1>(); } else cpwait<0>();
                __syncthreads();
                u32 AsU = dsmU + cur*21760;
                u32 BsU = AsU + 17408;
                int kb = wg*64;
                #pragma unroll
                for(int kk=0;kk<64;kk+=16){
                    u32 a[4], bb[4];
                    ldm_x4(a, AsU + ((w4*16+arow)*KST + kb+kk + acol)*2);
                    ldm_x4(bb, BsU + ((brow)*KST + kb+kk + bcol)*2);
                    mma16816(acc3[0], a, bb);
                    mma16816(acc3[1], a, bb+2);
                }
                __syncthreads();
            }
            float* ps = (float*)dsm;
            if(wg==1){
                #pragma unroll
                for(int nt=0;nt<2;nt++){
                    int r0=w4*16+g, c0=nt*8+tg*2;
                    ps[r0*20+c0]=acc3[nt][0]; ps[r0*20+c0+1]=acc3[nt][1];
                    ps[(r0+8)*20+c0]=acc3[nt][2]; ps[(r0+8)*20+c0+1]=acc3[nt][3];
                }
            }
            __syncthreads();
            if(wg==0){
                #pragma unroll
                for(int nt=0;nt<2;nt++){
                    int r0=w4*16+g, c0l=nt*8+tg*2;
                    int c0 = nb*16 + c0l;
                    float v0=tanhf(acc3[nt][0]+ps[r0*20+c0l]);
                    float v1=tanhf(acc3[nt][1]+ps[r0*20+c0l+1]);
                    float v2=tanhf(acc3[nt][2]+ps[(r0+8)*20+c0l]);
                    float v3=tanhf(acc3[nt][3]+ps[(r0+8)*20+c0l+1]);
                    bf16 b0=__float2bfloat16(v0), b1=__float2bfloat16(v1);
                    bf16 b2=__float2bfloat16(v2), b3=__float2bfloat16(v3);
                    g_outs[((size_t)t*B_ + r0)*H_ + c0]   = b0;
                    g_outs[((size_t)t*B_ + r0)*H_ + c0+1] = b1;
                    g_outs[((size_t)t*B_ + r0+8)*H_ + c0]   = b2;
                    g_outs[((size_t)t*B_ + r0+8)*H_ + c0+1] = b3;
                    g_acat[(size_t)r0*2048 + 1024 + c0]   = b0;
                    g_acat[(size_t)r0*2048 + 1024 + c0+1] = b1;
                    g_acat[(size_t)(r0+8)*2048 + 1024 + c0]   = b2;
                    g_acat[(size_t)(r0+8)*2048 + 1024 + c0+1] = b3;
                }
            }
        }
        gridBar(64, myGen);
    }
}

// ---------------- vocab (3-stage, single sync) ----------------
__global__ void __launch_bounds__(256) vocabKernel(const int* __restrict__ tgt)
{
    extern __shared__ __align__(16) bf16 vsm[];
    const int STG = 128*AS_;
    __shared__ float redm[4][2][2][8][2];
    __shared__ float reds[4][2][2][8][2];
    int tid=threadIdx.x, warp=tid>>5, lane=tid&31, g=lane>>2, tg=lane&3;
    int wr=warp>>1, wc=warp&1;
    LDM_SETUP();
    u32 vsmU = (u32)__cvta_generic_to_shared(vsm);
    int bm=blockIdx.y*128, bn=blockIdx.x*128, chunk=blockIdx.x;
    float acc[2][8][4];
    #pragma unroll
    for(int i=0;i<2;i++) for(int j=0;j<8;j++) for(int k=0;k<4;k++) acc[i][j][k]=0.f;

    auto ld = [&](int it, int s){
        bf16* As = vsm + s*2*STG; bf16* Bs = As + STG;
        #pragma unroll
        for(int i=tid;i<512;i+=256){ int r=i>>2, c=(i&3)*8;
            cpasync16(&As[r*AS_+c], g_outs + (size_t)(bm+r)*1024 + it*32 + c); }
        #pragma unroll
        for(int i=tid;i<512;i+=256){ int r=i>>2, c=(i&3)*8;
            cpasync16(&Bs[r*AS_+c], g_Wvoc + (size_t)(bn+r)*1024 + it*32 + c); }
        cpcommit();
    };
    ld(0,0); ld(1,1);
    for(int it=0; it<32; it++){
        if(it<31) cpwait<1>(); else cpwait<0>();
        __syncthreads();
        if(it+2<32) ld(it+2, (it+2)%3);
        u32 AsU = vsmU + (it%3)*2*STG*2; u32 BsU = AsU + STG*2;
        #pragma unroll
        for(int kk=0;kk<32;kk+=16){
            u32 a[2][4], b[8][2];
            #pragma unroll
            for(int mi=0;mi<2;mi++)
                ldm_x4(a[mi], AsU + ((wr*32+mi*16+arow)*AS_ + kk + acol)*2);
            #pragma unroll
            for(int nj=0;nj<4;nj++)
                ldm_x4(&b[nj*2][0], BsU + ((wc*64+nj*16+brow)*AS_ + kk + bcol)*2);
            #pragma unroll
            for(int mi=0;mi<2;mi++)
                #pragma unroll
                for(int ni=0;ni<8;ni++)
                    mma16816(acc[mi][ni], a[mi], b[ni]);
        }
    }
    __syncthreads();
    #pragma unroll
    for(int mi=0;mi<2;mi++) for(int h=0;h<2;h++){
        float m=-1e30f;
        #pragma unroll
        for(int ni=0;ni<8;ni++) m=fmaxf(m, fmaxf(acc[mi][ni][h*2], acc[mi][ni][h*2+1]));
        m=fmaxf(m, __shfl_xor_sync(0xffffffffu,m,1));
        m=fmaxf(m, __shfl_xor_sync(0xffffffffu,m,2));
        if(tg==0) redm[wr][mi][h][g][wc]=m;
    }
    __syncthreads();
    #pragma unroll
    for(int mi=0;mi<2;mi++) for(int h=0;h<2;h++){
        float M=fmaxf(redm[wr][mi][h][g][0], redm[wr][mi][h][g][1]);
        float s=0.f;
        #pragma unroll
        for(int ni=0;ni<8;ni++){
            s+=expf(acc[mi][ni][h*2]-M);
            s+=expf(acc[mi][ni][h*2+1]-M);
        }
        s+=__shfl_xor_sync(0xffffffffu,s,1);
        s+=__shfl_xor_sync(0xffffffffu,s,2);
        if(tg==0) reds[wr][mi][h][g][wc]=s;
    }
    __syncthreads();
    if(wc==0 && tg==0){
        #pragma unroll
        for(int mi=0;mi<2;mi++) for(int h=0;h<2;h++){
            int grow = bm + wr*32 + mi*16 + h*8 + g;
            if(grow < TD_*B_){
                float M=fmaxf(redm[wr][mi][h][g][0], redm[wr][mi][h][g][1]);
                float S=reds[wr][mi][h][g][0]+reds[wr][mi][h][g][1];
                g_pmax[(size_t)grow*NCH+chunk]=M;
                g_psum[(size_t)grow*NCH+chunk]=S;
            }
        }
    }
    #pragma unroll
    for(int mi=0;mi<2;mi++) for(int h=0;h<2;h++){
        int grow = bm + wr*32 + mi*16 + h*8 + g;
        if(grow < TD_*B_){
            int gi = tgt[grow + 64];
            #pragma unroll
            for(int ni=0;ni<8;ni++){
                int c0 = bn + wc*64 + ni*8 + tg*2;
                if(c0==gi)   g_pgold[grow]=acc[mi][ni][h*2];
                if(c0+1==gi) g_pgold[grow]=acc[mi][ni][h*2+1];
            }
        }
    }
}

// ---------------- small kernels ----------------
__global__ void hcatK(){
    int i=blockIdx.x*blockDim.x+threadIdx.x;
    if(i>=B_*2048) return;
    int b=i>>11, j=i&2047;
    float hv = (j<1024)? g_hf[b*1024+j] : g_hb[b*1024+j-1024];
    float cv = (j<1024)? g_cf[b*1024+j] : g_cb[b*1024+j-1024];
    g_hcat[i]=__float2bfloat16(hv);
    g_ccat[i]=__float2bfloat16(cv);
}
__global__ void finalReduceK(const int* __restrict__ tgt, float* __restrict__ out){
    __shared__ float sm[64];
    int b=blockIdx.x, t=threadIdx.x;
    float v=0.f;
    if(t<TD_){
        int row=t*64+b;
        float m=-1e30f;
        for(int j=0;j<NCH;j++) m=fmaxf(m, g_pmax[(size_t)row*NCH+j]);
        float s=0.f;
        for(int j=0;j<NCH;j++) s+=g_psum[(size_t)row*NCH+j]*expf(g_pmax[(size_t)row*NCH+j]-m);
        float gold = g_pgold[row] - (m + logf(s));
        v = (tgt[row+64]!=0)? gold : 0.f;
    }
    sm[t]=v; __syncthreads();
    for(int o=32;o;o>>=1){ if(t<o) sm[t]+=sm[t+o]; __syncthreads(); }
    if(t==0) out[b]=sm[0];
}

// ---------------- host ----------------
template<typename Ty, size_t N> static Ty* gp(Ty (&arr)[N]){
    void* p=nullptr; cudaGetSymbolAddress(&p, arr); return (Ty*)p;
}
#define ENC_SMEM ((64*EST + 2*64*AST)*2)
#define G128_SMEM (3*2*128*AS_*2)
#define DEC_SMEM (2*34816)

extern "C" void kernel_launch(void* const* d_in, const int* in_sizes, int n_in,
                              void* d_out, int out_size){
    (void)in_sizes; (void)n_in; (void)out_size;
    const int* src  = (const int*)d_in[0];
    const int* tgt  = (const int*)d_in[1];
    const int* lens = (const int*)d_in[2];
    const float* src_embed=(const float*)d_in[3];
    const float* dst_embed=(const float*)d_in[4];
    const float* WihF=(const float*)d_in[5];
    const float* WhhF=(const float*)d_in[6];
    const float* bihF=(const float*)d_in[7];
    const float* bhhF=(const float*)d_in[8];
    const float* WihB=(const float*)d_in[9];
    const float* WhhB=(const float*)d_in[10];
    const float* bihB=(const float*)d_in[11];
    const float* bhhB=(const float*)d_in[12];
    const float* Wihd=(const float*)d_in[13];
    const float* Whhd=(const float*)d_in[14];
    const float* bihd=(const float*)d_in[15];
    const float* bhhd=(const float*)d_in[16];
    const float* Whp =(const float*)d_in[17];
    const float* Wcp =(const float*)d_in[18];
    const float* Watt=(const float*)d_in[19];
    const float* Wcmb=(const float*)d_in[20];
    const float* Wvoc=(const float*)d_in[21];
    float* out=(float*)d_out;

    bf16 *sWihF=gp(g_WihF), *sWihB=gp(g_WihB);
    bf16 *sWihd=gp(g_Wihd);
    bf16 *sWatt=gp(g_Watt);
    float *sbF=gp(g_bEncF), *sbB=gp(g_bEncB), *sbD=gp(g_bDec);
    bf16 *sXg=gp(g_Xg), *sYg=gp(g_Yg);
    float *sGxF=gp(g_GxF), *sGxB=gp(g_GxB), *sGy=gp(g_Gy);
    bf16 *sench=gp(g_ench), *sencp=gp(g_encproj);
    bf16 *shcat=gp(g_hcat), *sccat=gp(g_ccat);
    float *scdec=gp(g_cdec);
    bf16 *sacat=gp(g_acat);

    static int attrSet = 0;
    if(!attrSet){
        cudaFuncSetAttribute(encPersist, cudaFuncAttributeMaxDynamicSharedMemorySize, ENC_SMEM);
        cudaFuncSetAttribute(gemm128, cudaFuncAttributeMaxDynamicSharedMemorySize, G128_SMEM);
        cudaFuncSetAttribute(vocabKernel, cudaFuncAttributeMaxDynamicSharedMemorySize, G128_SMEM);
        cudaFuncSetAttribute(decPersist, cudaFuncAttributeMaxDynamicSharedMemorySize, DEC_SMEM);
        attrSet = 1;
    }

    prepK<<<2048,256>>>(WihF,WhhF,WihB,WhhB,Wihd,Whhd,Whp,Wcp,Watt,Wcmb,Wvoc,
                        bihF,bhhF,bihB,bhhB,bihd,bhhd,
                        src, tgt, src_embed, dst_embed);
    gemm128<<<dim3(32,32),256,G128_SMEM>>>(sXg,E_, sWihF,E_, sGxF,G_,0, 1, sbF, E_);
    gemm128<<<dim3(32,32),256,G128_SMEM>>>(sXg,E_, sWihB,E_, sGxB,G_,0, 1, sbB, E_);
    gemm128<<<dim3(32,32),256,G128_SMEM>>>(sYg,E_, sWihd,1536, sGy,G_,0, 1, sbD, E_);
    barResetK<<<1,1>>>();
    encPersist<<<128,256,ENC_SMEM>>>(lens);
    hcatK<<<512,256>>>();
    gemm64<<<dim3(16,1),128>>>(shcat,2048, gp(g_Whp),2048, (float*)sacat,2048,1, 2048);
    gemm64<<<dim3(16,1),128>>>(sccat,2048, gp(g_Wcp),2048, scdec,H_,0, 2048);
    gemm128<<<dim3(8,32),256,G128_SMEM>>>(sench,2048, sWatt,2048, (float*)sencp,H_,1, 0, nullptr, 2048);
    barResetK<<<1,1>>>();
    decPersist<<<64,256,DEC_SMEM>>>(lens);
    vocabKernel<<<dim3(NCH, 32),256,G128_SMEM>>>(tgt);
    finalReduceK<<<64,64>>>(tgt, out);
}